// round 17
// baseline (speedup 1.0000x reference)
#include <cuda_runtime.h>
#include <math.h>
#include <stdint.h>
#include <stddef.h>

// DBN beat decoder, prefix-sum collapsed Viterbi, 2 barriers/chunk.
// tau = 28..109 (82 tempi), S = 5617, B = 4, T = 6000.
#define NI     82
#define TROW   84        // trans_t row stride (i-major)
#define LR     85        // Lbuf row stride
#define LBSZ   (CHUNK * LR)
#define RB     84        // F ring row stride
#define RINGD  256
#define S_TOT  5617
#define T_LEN  6000
#define BATCH  4
#define TPB    1024
#define CHUNK  28
#define NCH    215       // chunks cover t = 1..5999 (last has 7 frames)
#define NTOPS  2296      // 28*82 tasks
#define QSZ    (CHUNK * RB)   // 2352, one partial plane
#define BTH    882       // B threads: 3 i-slices x 21 j-quads x 14 f-pairs
#define STH    142       // stale-A threads
#define NSTALE 1890      // A tasks with g < j (read old Fring entries)

__device__ float g_L[(size_t)BATCH * T_LEN * NI];   // L values for lazy backtrace

__device__ __forceinline__ int first_of(int j) { return 28 * j + (j * (j - 1)) / 2; }

__global__ __launch_bounds__(TPB, 1)
void dbn_kernel(const float* __restrict__ logit, float* __restrict__ out)
{
    extern __shared__ char smraw[];
    float* trans_t = (float*)smraw;                 // [84][84] trans_t[i][j]
    float* Fring   = trans_t + TROW * TROW;         // [256][84]  F_t[j] at (t&255)
    float* Lbuf    = Fring + RINGD * RB;            // [2][28][85] double-buffered
    float* Pbuf    = Lbuf + 2 * LBSZ;               // [3][28][84] B partials (+scan scratch)
    float* cum     = Pbuf + 3 * QSZ;                // 6000: inclusive scan of nlp
    float* blp     = cum + T_LEN;                   // 6000
    float* redv    = blp + T_LEN;                   // 32
    int*   redi    = (int*)(redv + 32);             // 32
    unsigned* staleT = (unsigned*)(redi + 32);      // 1890 packed stale tasks

    const int tid = threadIdx.x;
    const int b   = blockIdx.x;
    const float* lg = logit + (size_t)b * T_LEN;
    float* Lg   = g_L + (size_t)b * T_LEN * NI;
    float* outb = out + (size_t)b * T_LEN;

    // ================= setup =================
    if (tid < NI) {               // trans row i = tid (fp64, matches numpy)
        double ti = (double)(28 + tid);
        double sum = 0.0;
        for (int jj = 0; jj < NI; ++jj)
            sum += exp(-100.0 * fabs((double)(28 + jj) / ti - 1.0));
        double ls = log(sum);
        for (int jj = 0; jj < NI; ++jj) {
            double rr = -100.0 * fabs((double)(28 + jj) / ti - 1.0);
            trans_t[tid * TROW + jj] = (float)(rr - ls);
        }
        trans_t[tid * TROW + 82] = -1e30f;
        trans_t[tid * TROW + 83] = -1e30f;
    }
    for (int t = tid; t < T_LEN; t += TPB) {
        float x  = lg[t];
        float l1 = log1pf(expf(-fabsf(x)));
        blp[t] = fminf(x, 0.0f) - l1;
        cum[t] = fminf(-x, 0.0f) - l1;     // nlp, scanned in place below
    }
    // stale task table: tasks (g,j) with g<j, ordered by (j,g)
    for (int k = tid; k < NTOPS; k += TPB) {
        int g = k / NI, j = k - g * NI;
        if (g < j) {
            int base = (j <= 28) ? (j * (j - 1)) / 2 : 378 + 28 * (j - 28);
            staleT[base + g] = ((unsigned)g << 16) | ((unsigned)j << 8)
                             | (unsigned)(g - 28 - j + 128);
        }
    }
    __syncthreads();

    // ---- block-wide inclusive scan of cum[0..5999] (6 elems/thread) ----
    {
        float* part  = Pbuf;          // 1000 scratch
        float* gpart = Pbuf + 1024;   // 32 scratch
        if (tid < 1000) {
            int base = 6 * tid;
            float a = cum[base];
            cum[base] = a;
            for (int k = 1; k < 6; ++k) { a += cum[base + k]; cum[base + k] = a; }
            part[tid] = a;
        }
        __syncthreads();
        if (tid < 32) {
            float acc = 0.0f;
            for (int k = 0; k < 32; ++k) {
                int idx = 32 * tid + k;
                if (idx < 1000) { float v = part[idx]; part[idx] = acc; acc += v; }
            }
            float x = acc;
#pragma unroll
            for (int off = 1; off < 32; off <<= 1) {
                float y = __shfl_up_sync(0xffffffffu, x, off);
                if ((tid & 31) >= off) x += y;
            }
            gpart[tid] = x - acc;    // exclusive group offset
        }
        __syncthreads();
        if (tid < 1000) {
            float off = part[tid] + gpart[tid >> 5];
            int base = 6 * tid;
#pragma unroll
            for (int k = 0; k < 6; ++k) cum[base + k] += off;
        }
    }
    __syncthreads();

    const float logS = logf((float)S_TOT);
    if (tid < NI) Fring[0 * RB + tid] = blp[0] - logS;   // F_0[j]

    // ---- per-thread chunk-invariant constants ----
    // combine tasks (3/thread): task = f*82 + j
    int Kf[3], Kj[3], Kpb[3];
#pragma unroll
    for (int m = 0; m < 3; ++m) {
        int task = 3 * tid + m;
        if (task < NTOPS) {
            int f = task / NI, j = task - f * NI;
            Kf[m] = f; Kj[m] = j; Kpb[m] = f * RB + j;
        } else { Kf[m] = 28; Kj[m] = 0; Kpb[m] = 0; }
    }
    // B mapping (tid < BTH): i-slice h, j-quad jq, frame pair f0
    const int h    = tid / 294;
    const int brem = tid - h * 294;
    const int jq   = brem / 14;
    const int f0   = 2 * (brem - 14 * jq);
    const int Bi0  = (h == 0) ? 0 : (h == 1) ? 28 : 55;
    const int Bi1  = (h == 0) ? 28 : (h == 1) ? 55 : 82;
    __syncthreads();

    // ---- priming: all A tasks for chunk 0 (t0 = 1) into Lbuf[0] ----
#pragma unroll
    for (int m = 0; m < 3; ++m) {
        int task = 3 * tid + m;
        if (task < NTOPS) {
            int g = task / NI, j = task - g * NI;
            int st = 1 + g - 28 - j;
            float ce = cum[g];               // cum[t0 + g - 1], t0 = 1
            float v = (st >= 0) ? Fring[(st & (RINGD - 1)) * RB + j] + (ce - cum[st])
                                : ce - logS;
            Lbuf[g * LR + j] = v;
            Lg[(size_t)(1 + g) * NI + j] = v;
        }
    }
    __syncthreads();

    // ================= 215 chunks, 2 barriers each =================
    for (int c = 0; c < NCH; ++c) {
        const int t0  = 1 + CHUNK * c;
        int NF = T_LEN - t0; if (NF > CHUNK) NF = CHUNK;
        const int t0n = t0 + CHUNK;
        int NFn = (c + 1 < NCH) ? (T_LEN - t0n) : 0;
        if (NFn > CHUNK) NFn = CHUNK;
        const float* Lcur = Lbuf + (c & 1) * LBSZ;
        float*       Lnxt = Lbuf + ((c + 1) & 1) * LBSZ;
        float* Lgn = Lg + (size_t)t0n * NI;

        // ---- P1: B (tid<882) || stale-A for next chunk (tid>=882) ----
        if (tid < BTH) {
            const float4* tc = (const float4*)trans_t + jq;
            const float*  L0 = Lcur + f0 * LR;
            const float*  L1 = L0 + LR;
            float4 A0 = make_float4(-1e30f, -1e30f, -1e30f, -1e30f);
            float4 A1 = A0;
#pragma unroll 4
            for (int i = Bi0; i < Bi1; ++i) {
                float4 tv = tc[i * (TROW / 4)];
                float l0 = L0[i];
                float l1 = L1[i];
                A0.x = fmaxf(A0.x, l0 + tv.x); A0.y = fmaxf(A0.y, l0 + tv.y);
                A0.z = fmaxf(A0.z, l0 + tv.z); A0.w = fmaxf(A0.w, l0 + tv.w);
                A1.x = fmaxf(A1.x, l1 + tv.x); A1.y = fmaxf(A1.y, l1 + tv.y);
                A1.z = fmaxf(A1.z, l1 + tv.z); A1.w = fmaxf(A1.w, l1 + tv.w);
            }
            float* Ph = Pbuf + h * QSZ;
            *(float4*)(Ph + f0 * RB + 4 * jq)       = A0;
            *(float4*)(Ph + (f0 + 1) * RB + 4 * jq) = A1;
        } else {
#pragma unroll 2
            for (int it = 0; it < 14; ++it) {
                int k = (tid - BTH) + STH * it;
                if (k < NSTALE) {
                    unsigned w = staleT[k];
                    int g = (int)(w >> 16), j = (int)((w >> 8) & 0xFF);
                    int D = (int)(w & 0xFF) - 128;
                    if (g < NFn) {
                        int st = t0n + D;
                        float ce = cum[t0n + g - 1];
                        float v = (st >= 0)
                            ? Fring[(st & (RINGD - 1)) * RB + j] + (ce - cum[st])
                            : ce - logS;
                        Lnxt[g * LR + j] = v;
                        Lgn[g * NI + j] = v;
                    }
                }
            }
        }
        __syncthreads();

        // ---- P2: combine (F write) + fused fresh-A for next chunk ----
#pragma unroll
        for (int m = 0; m < 3; ++m) {
            if (Kf[m] < NF) {
                int f = Kf[m], j = Kj[m];
                float v = fmaxf(fmaxf(Pbuf[Kpb[m]], Pbuf[QSZ + Kpb[m]]),
                                Pbuf[2 * QSZ + Kpb[m]]) + blp[t0 + f];
                Fring[((t0 + f) & (RINGD - 1)) * RB + j] = v;
                int gp = f + j;                 // fresh task g' = f + j
                if (gp < NFn) {
                    float v2 = v + (cum[t0 + 27 + gp] - cum[t0 + f]);
                    Lnxt[gp * LR + j] = v2;
                    Lgn[gp * NI + j] = v2;
                }
            }
        }
        __syncthreads();
    }

    // ================= final argmax over delta_{T-1} (first-max) ==========
    for (int t = tid; t < T_LEN; t += TPB) outb[t] = 0.0f;

    const float cend = cum[T_LEN - 1];
    float bv = -INFINITY; int bs = 0x7fffffff;
    for (int s = tid; s < S_TOT; s += TPB) {
        int lo = 0, hi = 81;
        while (lo < hi) { int mid = (lo + hi + 1) >> 1; if (first_of(mid) <= s) lo = mid; else hi = mid - 1; }
        int j = lo;
        int p = s - first_of(j);
        int tf = T_LEN - 1 - p;
        float v = Fring[(tf & (RINGD - 1)) * RB + j] + (cend - cum[tf]);
        if (v > bv) { bv = v; bs = s; }
    }
#pragma unroll
    for (int off = 16; off; off >>= 1) {
        float ov = __shfl_xor_sync(0xffffffffu, bv, off);
        int   oi = __shfl_xor_sync(0xffffffffu, bs, off);
        if (ov > bv || (ov == bv && oi < bs)) { bv = ov; bs = oi; }
    }
    if ((tid & 31) == 0) { redv[tid >> 5] = bv; redi[tid >> 5] = bs; }
    __syncthreads();

    // ================= warp-cooperative lazy backtrace =====================
    if (tid < 32) {
        bv = redv[tid]; bs = redi[tid];
#pragma unroll
        for (int off = 16; off; off >>= 1) {
            float ov = __shfl_xor_sync(0xffffffffu, bv, off);
            int   oi = __shfl_xor_sync(0xffffffffu, bs, off);
            if (ov > bv || (ov == bv && oi < bs)) { bv = ov; bs = oi; }
        }
        int lo = 0, hi = 81;
        while (lo < hi) { int mid = (lo + hi + 1) >> 1; if (first_of(mid) <= bs) lo = mid; else hi = mid - 1; }
        int j   = lo;
        int pos = bs - first_of(j);
        int t   = T_LEN - 1;
        const int lane = tid;

        while (true) {
            int te = t - pos;
            if (te < 0) break;
            if (lane == 0) {
                float x  = lg[te];
                float sg = 1.0f / (1.0f + expf(-x));
                if (sg >= 0.05f) outb[te] = 1.0f;
            }
            if (te == 0) break;
            const float* Lr = Lg + (size_t)te * NI;
            float best = -INFINITY; int bi = 0x7fffffff;
            for (int i = lane; i < NI; i += 32) {
                float cc = Lr[i] + trans_t[i * TROW + j];
                if (cc > best) { best = cc; bi = i; }
            }
#pragma unroll
            for (int off = 16; off; off >>= 1) {
                float ov = __shfl_xor_sync(0xffffffffu, best, off);
                int   oi = __shfl_xor_sync(0xffffffffu, bi,   off);
                if (ov > best || (ov == best && oi < bi)) { best = ov; bi = oi; }
            }
            j   = bi;
            pos = 27 + j;
            t   = te - 1;
        }
    }
}

extern "C" void kernel_launch(void* const* d_in, const int* in_sizes, int n_in,
                              void* d_out, int out_size)
{
    (void)in_sizes; (void)n_in; (void)out_size;
    const float* logit = (const float*)d_in[0];
    float* out = (float*)d_out;

    const size_t smem = (size_t)(TROW * TROW + RINGD * RB + 2 * LBSZ
                                 + 3 * QSZ + 2 * T_LEN + 64 + NSTALE) * 4;
    cudaFuncSetAttribute(dbn_kernel,
                         cudaFuncAttributeMaxDynamicSharedMemorySize, (int)smem);
    dbn_kernel<<<BATCH, TPB, smem>>>(logit, out);
}